// round 16
// baseline (speedup 1.0000x reference)
#include <cuda_runtime.h>
#include <cuda_fp16.h>
#include <cstdint>

#define PB 16
#define PD 256
#define PT 4096
#define PK 2048
#define PBT (PB*PT)
#define NDEC (PB*PD*PT)
#define EPSV 1e-5f
#define THRESH_M 0.08f

__device__ float g_emb[PK*PD];
__device__ float g_he2[PK];
__device__ __half g_emb_h[PK*PD];
__device__ int g_flag[PBT];
__device__ int g_nflag;
__device__ unsigned long long g_best[PBT];

__device__ __forceinline__ uint32_t smem_u32(const void* p){
    uint32_t a; asm("{ .reg .u64 t; cvta.to.shared.u64 t, %1; cvt.u32.u64 %0, t; }":"=r"(a):"l"(p)); return a; }
#define CPA(dst,src) asm volatile("cp.async.cg.shared.global [%0],[%1],16;"::"r"(dst),"l"(src):"memory")
#define CPC() asm volatile("cp.async.commit_group;":::"memory")
#define CPW1() asm volatile("cp.async.wait_group 1;":::"memory")
#define CPW0() asm volatile("cp.async.wait_group 0;":::"memory")
#define MMA(d,a,b0,b1) asm volatile( \
  "mma.sync.aligned.m16n8k16.row.col.f32.f16.f16.f32 {%0,%1,%2,%3},{%4,%5,%6,%7},{%8,%9},{%0,%1,%2,%3};" \
  : "+f"((d)[0]),"+f"((d)[1]),"+f"((d)[2]),"+f"((d)[3]) \
  : "r"((a)[0]),"r"((a)[1]),"r"((a)[2]),"r"((a)[3]),"r"(b0),"r"(b1))
#define LDSM4(r0,r1,r2,r3,addr) asm volatile( \
  "ldmatrix.sync.aligned.m8n8.x4.shared.b16 {%0,%1,%2,%3},[%4];" \
  : "=r"(r0),"=r"(r1),"=r"(r2),"=r"(r3) : "r"(addr))

// ---------- prep ----------
__global__ void prep_emb_kernel(const float* __restrict__ es, const float* __restrict__ cu){
    int k=blockIdx.x, d=threadIdx.x;
    if(k==0 && d==0) g_nflag=0;
    float v = __fdiv_rn(es[k*PD+d], fmaxf(cu[k], EPSV));
    g_emb[k*PD+d]=v;
    float cl = fminf(fmaxf(v,-60000.f),60000.f);
    g_emb_h[k*PD+d]=__float2half_rn(cl);
    __shared__ float red[256];
    red[d]=v*v; __syncthreads();
    #pragma unroll
    for(int s=128;s>0;s>>=1){ if(d<s) red[d]+=red[d+s]; __syncthreads(); }
    if(d==0) g_he2[k]=0.5f*red[0];
}

// ---------- main: fp16 HMMA + fused argmin, 2 CTAs/SM, wait-shadowed pipeline ----------
#define SEO 67584
#define SRD 104448
#define SMEMB 105984

__global__ void __launch_bounds__(256,2)
argmin_mma_kernel(const float* __restrict__ x){
    extern __shared__ char smem[];
    uint32_t sb = smem_u32(smem);
    const int tid=threadIdx.x, lane=tid&31, wid=tid>>5;
    const int wm=wid&3, wn=wid>>2, lr=lane>>2, lc=lane&3;
    const int row0=blockIdx.x*128;
    const int lrow=lane&15, lkoff=(lane>>4)*16;
    float* sb1=(float*)(smem+SRD); float* sb2=sb1+128; int* sk=(int*)(sb2+128);

    // --- prologue: stage x fp32 into B area, convert -> resident fp16 A tile ---
    {
        const int bb=row0>>12, t0v=row0&4095;
        const float* xsrc = x + ((long)bb<<20) + t0v;
        const int tpart=tid&127, half_=tid>>7;
        for(int c=0;c<4;c++){
            #pragma unroll
            for(int j=0;j<8;j++){ int id=j*256+tid; int d=id>>5, c16=id&31;
                CPA(sb+SEO + d*512 + c16*16, xsrc + (long)(c*64+d)*4096 + c16*4); }
            CPC(); CPW0();
            __syncthreads();
            const float* stg=(const float*)(smem+SEO);
            #pragma unroll
            for(int q=0;q<16;q++){
                int dl=half_*32+2*q;
                float f0=stg[dl*128+tpart], f1=stg[(dl+1)*128+tpart];
                __half2 h2=__floats2half2_rn(f0,f1);
                *(__half2*)(smem + tpart*528 + (c*64+dl)*2) = h2;
            }
            __syncthreads();
        }
    }
    // emb chunk 0 -> stage 0
    #pragma unroll
    for(int j=0;j<4;j++){ int id=j*256+tid; int row=id>>3, c=id&7;
        CPA(sb+SEO+row*144+c*16, g_emb_h+((long)row<<8)+c*8); }
    CPC();

    float b1v[4], b2v[4]; int bkv[4];
    #pragma unroll
    for(int i=0;i<4;i++){ b1v[i]=-3.4e38f; b2v[i]=-3.4e38f; bkv[i]=0; }

    for(int kt=0;kt<16;kt++){
        float acc[2][8][4];
        #pragma unroll
        for(int a=0;a<2;a++)
            #pragma unroll
            for(int b=0;b<8;b++)
                #pragma unroll
                for(int c=0;c<4;c++) acc[a][b][c]=0.f;
        for(int dc=0;dc<4;dc++){
            int s=kt*4+dc;
            __syncthreads();      // compute(s-1) done -> safe to overwrite buf (s+1)&1
            if(s+1<64){
                int ns=s+1, nk=ns>>2, nd=ns&3, nb=ns&1;
                #pragma unroll
                for(int j=0;j<4;j++){ int id=j*256+tid; int row=id>>3, c=id&7;
                    CPA(sb+SEO+nb*18432+row*144+c*16,
                        g_emb_h+(((long)(nk*128+row))<<8)+nd*64+c*8); }
                CPC();
                CPW1();           // group(s) done; group(s+1) still in flight
            } else {
                CPW0();
            }
            __syncthreads();      // load(s) visible to all warps
            uint32_t ebu = sb + SEO + (s&1)*18432;
            #pragma unroll
            for(int ks=0;ks<4;ks++){
                uint32_t ah[2][4];
                #pragma unroll
                for(int mt=0;mt<2;mt++){
                    uint32_t aa = sb + (wm*32+mt*16+lrow)*528 + dc*128 + ks*32 + lkoff;
                    LDSM4(ah[mt][0],ah[mt][1],ah[mt][2],ah[mt][3], aa);
                }
                #pragma unroll
                for(int p=0;p<4;p++){
                    uint32_t ba = ebu + (wn*64+p*16+lrow)*144 + ks*32 + lkoff;
                    uint32_t h0,h1,h2,h3;
                    LDSM4(h0,h1,h2,h3, ba);
                    #pragma unroll
                    for(int mt=0;mt<2;mt++){
                        MMA(acc[mt][2*p],   ah[mt], h0, h2);
                        MMA(acc[mt][2*p+1], ah[mt], h1, h3);
                    }
                }
            }
        }
        #pragma unroll
        for(int nt=0;nt<8;nt++){
            int kb = wn*64 + nt*8 + lc*2;
            int k0 = kt*128 + kb;
            float hea = __ldg(&g_he2[k0]), heb = __ldg(&g_he2[k0+1]);
            #pragma unroll
            for(int mt=0;mt<2;mt++)
                #pragma unroll
                for(int h=0;h<2;h++){
                    int idx=mt*2+h;
                    float v0 = acc[mt][nt][2*h+0]-hea;
                    float v1 = acc[mt][nt][2*h+1]-heb;
                    if(v0>b1v[idx]){ b2v[idx]=b1v[idx]; b1v[idx]=v0; bkv[idx]=k0; }
                    else if(v0>b2v[idx]) b2v[idx]=v0;
                    if(v1>b1v[idx]){ b2v[idx]=b1v[idx]; b1v[idx]=v1; bkv[idx]=k0+1; }
                    else if(v1>b2v[idx]) b2v[idx]=v1;
                }
        }
    }
    #pragma unroll
    for(int off=1;off<4;off<<=1)
        #pragma unroll
        for(int i=0;i<4;i++){
            float ob1=__shfl_xor_sync(0xffffffffu,b1v[i],off);
            float ob2=__shfl_xor_sync(0xffffffffu,b2v[i],off);
            int obk=__shfl_xor_sync(0xffffffffu,bkv[i],off);
            if(ob1>b1v[i]){ b2v[i]=fmaxf(b1v[i],ob2); b1v[i]=ob1; bkv[i]=obk; }
            else b2v[i]=fmaxf(b2v[i],ob1);
        }
    if(wn==1 && lc==0){
        #pragma unroll
        for(int i=0;i<4;i++){ int r=wm*32+(i>>1)*16+(i&1)*8+lr; sb1[r]=b1v[i]; sb2[r]=b2v[i]; sk[r]=bkv[i]; }
    }
    __syncthreads();
    if(wn==0 && lc==0){
        #pragma unroll
        for(int i=0;i<4;i++){
            int r=wm*32+(i>>1)*16+(i&1)*8+lr;
            float ob1=sb1[r], ob2=sb2[r]; int obk=sk[r];
            if(ob1>b1v[i]){ b2v[i]=fmaxf(b1v[i],ob2); b1v[i]=ob1; bkv[i]=obk; }
            else b2v[i]=fmaxf(b2v[i],ob1);
            int row=row0+r;
            if(b1v[i]-b2v[i] < THRESH_M){
                g_best[row]=~0ull;
                int p=atomicAdd(&g_nflag,1); g_flag[p]=row;
            } else {
                g_best[row]=(unsigned long long)(uint32_t)bkv[i];
            }
        }
    }
}

// ---------- recheck v4: 8-row batches, 16 k-slices, double-buffered es ----------
#define RXS 0
#define RES 16384
#define RRV 53248
#define RRK 57344
#define RSH 61440
#define RSR 61952
#define RSMEM 62976

__global__ void __launch_bounds__(256,1) recheck_kernel(const float* __restrict__ x){
    extern __shared__ char smem[];
    uint32_t sb = smem_u32(smem);
    float* xs=(float*)(smem+RXS);            // [256 d][8 rows]
    float* rv=(float*)(smem+RRV);            // [128 ty][8 rows]
    int*   rk=(int*)(smem+RRK);
    float* she=(float*)(smem+RSH);           // [128]
    int*  srows=(int*)(smem+RSR);            // [8]
    int tid=threadIdx.x, tx=tid&1, ty=tid>>1;  // ty: 0..127 -> one k each
    int k0=blockIdx.y*128;
    int n=g_nflag;
    for(int base=blockIdx.x*8; base<n; base+=gridDim.x*8){
        int cnt=min(8,n-base);
        if(tid<8) srows[tid]=g_flag[base+min(tid,cnt-1)];
        __syncthreads();
        #pragma unroll
        for(int r=0;r<8;r++){ int i=tid&7, d=(tid>>3)+(r<<5);
            int row=srows[i]; int b=row>>12,t=row&4095;
            xs[d*8+i]=x[(((long)(b*PD+d))<<12)+t]; }
        if(tid<128) she[tid]=g_he2[k0+tid];
        #pragma unroll
        for(int j=0;j<4;j++){ int id=j*256+tid; int kk=id>>3, c8=id&7;
            CPA(sb+RES + kk*144 + c8*16, g_emb + (long)(k0+kk)*PD + c8*4); }
        CPC();
        float accr[4];
        #pragma unroll
        for(int i=0;i<4;i++) accr[i]=0.f;
        for(int dcB=0;dcB<8;dcB++){
            __syncthreads();
            if(dcB+1<8){
                int nb=(dcB+1)&1;
                #pragma unroll
                for(int j=0;j<4;j++){ int id=j*256+tid; int kk=id>>3, c8=id&7;
                    CPA(sb+RES+nb*18432 + kk*144 + c8*16,
                        g_emb + (long)(k0+kk)*PD + (dcB+1)*32 + c8*4); }
                CPC(); CPW1();
            } else CPW0();
            __syncthreads();
            const float* es=(const float*)(smem+RES+(dcB&1)*18432);
            #pragma unroll
            for(int d=0;d<32;d++){
                float4 xv=*(const float4*)&xs[(dcB*32+d)*8+tx*4];
                float e=es[ty*36+d];
                accr[0]=fmaf(xv.x,e,accr[0]);
                accr[1]=fmaf(xv.y,e,accr[1]);
                accr[2]=fmaf(xv.z,e,accr[2]);
                accr[3]=fmaf(xv.w,e,accr[3]);
            }
        }
        __syncthreads();
        #pragma unroll
        for(int i=0;i<4;i++){
            rv[ty*8+tx*4+i]=accr[i]-she[ty];
            rk[ty*8+tx*4+i]=k0+ty;
        }
        __syncthreads();
        if(tid<8){
            float bv=rv[tid]; int bk=rk[tid];
            for(int y=1;y<128;y++){ float v=rv[y*8+tid]; int kk=rk[y*8+tid];
                if(v>bv||(v==bv&&kk<bk)){ bv=v; bk=kk; } }
            if(tid<cnt){
                float s=-bv;
                uint32_t bits=__float_as_uint(s);
                uint32_t ord = bits ^ ((bits>>31) ? 0xFFFFFFFFu : 0x80000000u);
                unsigned long long key = ((unsigned long long)ord<<32) | (uint32_t)bk;
                atomicMin(&g_best[srows[tid]], key);
            }
        }
        __syncthreads();
    }
}

// ---------- outputs ----------
__global__ void decode_emit_kernel(float* __restrict__ dec, float* __restrict__ codes_out){
    int i = blockIdx.x*256+threadIdx.x;       // < PBT*32
    int t = i & 4095;
    int dg = (i>>12) & 31;
    int b = i >> 17;
    int code = (int)(g_best[b*PT+t]&0xFFFFFFFFull);
    const float* er = &g_emb[code*PD];
    float4 e0 = *(const float4*)&er[dg*4];
    float4 e1 = *(const float4*)&er[dg*4+128];
    if(dec){
        long base = ((long)b<<20) + ((long)dg<<14) + t;
        dec[base]          = e0.x;
        dec[base+4096]     = e0.y;
        dec[base+8192]     = e0.z;
        dec[base+12288]    = e0.w;
        long base2 = base + (1L<<19);
        dec[base2]         = e1.x;
        dec[base2+4096]    = e1.y;
        dec[base2+8192]    = e1.z;
        dec[base2+12288]   = e1.w;
    }
    if(codes_out && i<PBT) codes_out[i]=(float)(int)(g_best[i]&0xFFFFFFFFull);
}
__global__ void emit_codes_i_kernel(int* o){ int i=blockIdx.x*256+threadIdx.x; o[i]=(int)(g_best[i]&0xFFFFFFFFull); }

extern "C" void kernel_launch(void* const* d_in, const int* in_sizes, int n_in,
                              void* d_out, int out_size){
    const float* x=(const float*)d_in[0];
    const float* esum=(const float*)d_in[1];
    const float* cu=(const float*)d_in[2];

    prep_emb_kernel<<<PK,256>>>(esum,cu);

    cudaFuncSetAttribute(argmin_mma_kernel,cudaFuncAttributeMaxDynamicSharedMemorySize,SMEMB);
    cudaFuncSetAttribute(recheck_kernel,cudaFuncAttributeMaxDynamicSharedMemorySize,RSMEM);
    argmin_mma_kernel<<<PBT/128,256,SMEMB>>>(x);
    recheck_kernel<<<dim3(192,16),256,RSMEM>>>(x);

    float* codes_out=nullptr; float* dec_out=nullptr; bool ci=false;
    if(out_size==PBT+NDEC){ codes_out=(float*)d_out; dec_out=(float*)d_out+PBT; }
    else if(out_size==NDEC){ dec_out=(float*)d_out; }
    else if(out_size==PBT){ ci=true; }
    else { codes_out=(float*)d_out; if(out_size>=PBT+NDEC) dec_out=(float*)d_out+PBT; }

    if(dec_out||codes_out) decode_emit_kernel<<<(PBT*32)/256,256>>>(dec_out,codes_out);
    if(ci) emit_codes_i_kernel<<<PBT/256,256>>>((int*)d_out);
}

// round 17
// speedup vs baseline: 1.0524x; 1.0524x over previous
#include <cuda_runtime.h>
#include <cuda_fp16.h>
#include <cstdint>

#define PB 16
#define PD 256
#define PT 4096
#define PK 2048
#define PBT (PB*PT)
#define NDEC (PB*PD*PT)
#define EPSV 1e-5f
#define THRESH_M 0.08f

__device__ float g_emb[PK*PD];
__device__ float g_he2[PK];
__device__ __half g_emb_h[PK*PD];
__device__ int g_flag[PBT];
__device__ int g_nflag;
__device__ unsigned long long g_best[PBT];

__device__ __forceinline__ uint32_t smem_u32(const void* p){
    uint32_t a; asm("{ .reg .u64 t; cvta.to.shared.u64 t, %1; cvt.u32.u64 %0, t; }":"=r"(a):"l"(p)); return a; }
#define CPA(dst,src) asm volatile("cp.async.cg.shared.global [%0],[%1],16;"::"r"(dst),"l"(src):"memory")
#define CPC() asm volatile("cp.async.commit_group;":::"memory")
#define CPW1() asm volatile("cp.async.wait_group 1;":::"memory")
#define CPW0() asm volatile("cp.async.wait_group 0;":::"memory")
#define MMA(d,a,b0,b1) asm volatile( \
  "mma.sync.aligned.m16n8k16.row.col.f32.f16.f16.f32 {%0,%1,%2,%3},{%4,%5,%6,%7},{%8,%9},{%0,%1,%2,%3};" \
  : "+f"((d)[0]),"+f"((d)[1]),"+f"((d)[2]),"+f"((d)[3]) \
  : "r"((a)[0]),"r"((a)[1]),"r"((a)[2]),"r"((a)[3]),"r"(b0),"r"(b1))
#define LDSM4(r0,r1,r2,r3,addr) asm volatile( \
  "ldmatrix.sync.aligned.m8n8.x4.shared.b16 {%0,%1,%2,%3},[%4];" \
  : "=r"(r0),"=r"(r1),"=r"(r2),"=r"(r3) : "r"(addr))

// ---------- prep ----------
__global__ void prep_emb_kernel(const float* __restrict__ es, const float* __restrict__ cu){
    int k=blockIdx.x, d=threadIdx.x;
    if(k==0 && d==0) g_nflag=0;
    float v = __fdiv_rn(es[k*PD+d], fmaxf(cu[k], EPSV));
    g_emb[k*PD+d]=v;
    float cl = fminf(fmaxf(v,-60000.f),60000.f);
    g_emb_h[k*PD+d]=__float2half_rn(cl);
    __shared__ float red[256];
    red[d]=v*v; __syncthreads();
    #pragma unroll
    for(int s=128;s>0;s>>=1){ if(d<s) red[d]+=red[d+s]; __syncthreads(); }
    if(d==0) g_he2[k]=0.5f*red[0];
}

// ---------- main: fp16 HMMA + fused argmin, 2 CTAs/SM, single-sync pipeline ----------
#define SEO 67584
#define SRD 104448
#define SMEMB 105984

__global__ void __launch_bounds__(256,2)
argmin_mma_kernel(const float* __restrict__ x){
    extern __shared__ char smem[];
    uint32_t sb = smem_u32(smem);
    const int tid=threadIdx.x, lane=tid&31, wid=tid>>5;
    const int wm=wid&3, wn=wid>>2, lr=lane>>2, lc=lane&3;
    const int row0=blockIdx.x*128;
    const int lrow=lane&15, lkoff=(lane>>4)*16;
    float* sb1=(float*)(smem+SRD); float* sb2=sb1+128; int* sk=(int*)(sb2+128);

    // --- prologue: stage x fp32 into B area, convert -> resident fp16 A tile ---
    {
        const int bb=row0>>12, t0v=row0&4095;
        const float* xsrc = x + ((long)bb<<20) + t0v;
        const int tpart=tid&127, half_=tid>>7;
        for(int c=0;c<4;c++){
            #pragma unroll
            for(int j=0;j<8;j++){ int id=j*256+tid; int d=id>>5, c16=id&31;
                CPA(sb+SEO + d*512 + c16*16, xsrc + (long)(c*64+d)*4096 + c16*4); }
            CPC(); CPW0();
            __syncthreads();
            const float* stg=(const float*)(smem+SEO);
            #pragma unroll
            for(int q=0;q<16;q++){
                int dl=half_*32+2*q;
                float f0=stg[dl*128+tpart], f1=stg[(dl+1)*128+tpart];
                __half2 h2=__floats2half2_rn(f0,f1);
                *(__half2*)(smem + tpart*528 + (c*64+dl)*2) = h2;
            }
            __syncthreads();
        }
    }
    // emb chunk 0 -> stage 0
    #pragma unroll
    for(int j=0;j<4;j++){ int id=j*256+tid; int row=id>>3, c=id&7;
        CPA(sb+SEO+row*144+c*16, g_emb_h+((long)row<<8)+c*8); }
    CPC();

    float b1v[4], b2v[4]; int bkv[4];
    #pragma unroll
    for(int i=0;i<4;i++){ b1v[i]=-3.4e38f; b2v[i]=-3.4e38f; bkv[i]=0; }

    for(int kt=0;kt<16;kt++){
        float acc[2][8][4];
        #pragma unroll
        for(int a=0;a<2;a++)
            #pragma unroll
            for(int b=0;b<8;b++)
                #pragma unroll
                for(int c=0;c<4;c++) acc[a][b][c]=0.f;
        for(int dc=0;dc<4;dc++){
            int s=kt*4+dc;
            // single sync: load(s) visible AND compute(s-1) done (it read buf (s+1)&1)
            CPW0();
            __syncthreads();
            if(s+1<64){
                int ns=s+1, nk=ns>>2, nd=ns&3, nb=ns&1;
                #pragma unroll
                for(int j=0;j<4;j++){ int id=j*256+tid; int row=id>>3, c=id&7;
                    CPA(sb+SEO+nb*18432+row*144+c*16,
                        g_emb_h+(((long)(nk*128+row))<<8)+nd*64+c*8); }
                CPC();
            }
            uint32_t ebu = sb + SEO + (s&1)*18432;
            #pragma unroll
            for(int ks=0;ks<4;ks++){
                uint32_t ah[2][4];
                #pragma unroll
                for(int mt=0;mt<2;mt++){
                    uint32_t aa = sb + (wm*32+mt*16+lrow)*528 + dc*128 + ks*32 + lkoff;
                    LDSM4(ah[mt][0],ah[mt][1],ah[mt][2],ah[mt][3], aa);
                }
                #pragma unroll
                for(int p=0;p<4;p++){
                    uint32_t ba = ebu + (wn*64+p*16+lrow)*144 + ks*32 + lkoff;
                    uint32_t h0,h1,h2,h3;
                    LDSM4(h0,h1,h2,h3, ba);
                    #pragma unroll
                    for(int mt=0;mt<2;mt++){
                        MMA(acc[mt][2*p],   ah[mt], h0, h2);
                        MMA(acc[mt][2*p+1], ah[mt], h1, h3);
                    }
                }
            }
        }
        #pragma unroll
        for(int nt=0;nt<8;nt++){
            int kb = wn*64 + nt*8 + lc*2;
            int k0 = kt*128 + kb;
            float hea = __ldg(&g_he2[k0]), heb = __ldg(&g_he2[k0+1]);
            #pragma unroll
            for(int mt=0;mt<2;mt++)
                #pragma unroll
                for(int h=0;h<2;h++){
                    int idx=mt*2+h;
                    float v0 = acc[mt][nt][2*h+0]-hea;
                    float v1 = acc[mt][nt][2*h+1]-heb;
                    if(v0>b1v[idx]){ b2v[idx]=b1v[idx]; b1v[idx]=v0; bkv[idx]=k0; }
                    else if(v0>b2v[idx]) b2v[idx]=v0;
                    if(v1>b1v[idx]){ b2v[idx]=b1v[idx]; b1v[idx]=v1; bkv[idx]=k0+1; }
                    else if(v1>b2v[idx]) b2v[idx]=v1;
                }
        }
    }
    #pragma unroll
    for(int off=1;off<4;off<<=1)
        #pragma unroll
        for(int i=0;i<4;i++){
            float ob1=__shfl_xor_sync(0xffffffffu,b1v[i],off);
            float ob2=__shfl_xor_sync(0xffffffffu,b2v[i],off);
            int obk=__shfl_xor_sync(0xffffffffu,bkv[i],off);
            if(ob1>b1v[i]){ b2v[i]=fmaxf(b1v[i],ob2); b1v[i]=ob1; bkv[i]=obk; }
            else b2v[i]=fmaxf(b2v[i],ob1);
        }
    if(wn==1 && lc==0){
        #pragma unroll
        for(int i=0;i<4;i++){ int r=wm*32+(i>>1)*16+(i&1)*8+lr; sb1[r]=b1v[i]; sb2[r]=b2v[i]; sk[r]=bkv[i]; }
    }
    __syncthreads();
    if(wn==0 && lc==0){
        #pragma unroll
        for(int i=0;i<4;i++){
            int r=wm*32+(i>>1)*16+(i&1)*8+lr;
            float ob1=sb1[r], ob2=sb2[r]; int obk=sk[r];
            if(ob1>b1v[i]){ b2v[i]=fmaxf(b1v[i],ob2); b1v[i]=ob1; bkv[i]=obk; }
            else b2v[i]=fmaxf(b2v[i],ob1);
            int row=row0+r;
            if(b1v[i]-b2v[i] < THRESH_M){
                g_best[row]=~0ull;
                int p=atomicAdd(&g_nflag,1); g_flag[p]=row;
            } else {
                g_best[row]=(unsigned long long)(uint32_t)bkv[i];
            }
        }
    }
}

// ---------- recheck v3: 16-row batches, 16 k-slices, double-buffered es ----------
#define RXS 0
#define RES 16384
#define RRV 53248
#define RRK 57344
#define RSH 61440
#define RSR 61952
#define RSMEM 62976

__global__ void __launch_bounds__(256,1) recheck_kernel(const float* __restrict__ x){
    extern __shared__ char smem[];
    uint32_t sb = smem_u32(smem);
    float* xs=(float*)(smem+RXS);
    float* rv=(float*)(smem+RRV);
    int*   rk=(int*)(smem+RRK);
    float* she=(float*)(smem+RSH);
    int*  srows=(int*)(smem+RSR);
    int tid=threadIdx.x, tx=tid&3, ty=tid>>2;
    int k0=blockIdx.y*128;
    int n=g_nflag;
    for(int base=blockIdx.x*16; base<n; base+=gridDim.x*16){
        int cnt=min(16,n-base);
        if(tid<16) srows[tid]=g_flag[base+min(tid,cnt-1)];
        __syncthreads();
        for(int r=0;r<16;r++){ int i=tid&15, d=(tid>>4)+(r<<4);
            int row=srows[i]; int b=row>>12,t=row&4095;
            xs[d*16+i]=x[(((long)(b*PD+d))<<12)+t]; }
        if(tid<128) she[tid]=g_he2[k0+tid];
        #pragma unroll
        for(int j=0;j<4;j++){ int id=j*256+tid; int kk=id>>3, c8=id&7;
            CPA(sb+RES + kk*144 + c8*16, g_emb + (long)(k0+kk)*PD + c8*4); }
        CPC();
        float accr[4][2];
        #pragma unroll
        for(int i=0;i<4;i++){ accr[i][0]=0.f; accr[i][1]=0.f; }
        for(int dcB=0;dcB<8;dcB++){
            __syncthreads();
            if(dcB+1<8){
                int nb=(dcB+1)&1;
                #pragma unroll
                for(int j=0;j<4;j++){ int id=j*256+tid; int kk=id>>3, c8=id&7;
                    CPA(sb+RES+nb*18432 + kk*144 + c8*16,
                        g_emb + (long)(k0+kk)*PD + (dcB+1)*32 + c8*4); }
                CPC(); CPW1();
            } else CPW0();
            __syncthreads();
            const float* es=(const float*)(smem+RES+(dcB&1)*18432);
            #pragma unroll
            for(int d=0;d<32;d++){
                float4 xv=*(const float4*)&xs[(dcB*32+d)*16+tx*4];
                float xr[4]={xv.x,xv.y,xv.z,xv.w};
                #pragma unroll
                for(int j=0;j<2;j++){ float e=es[(ty*2+j)*36+d];
                    #pragma unroll
                    for(int i=0;i<4;i++) accr[i][j]=fmaf(xr[i],e,accr[i][j]); }
            }
        }
        __syncthreads();
        #pragma unroll
        for(int i=0;i<4;i++){
            float bb=-3.4e38f; int bk=1<<30;
            #pragma unroll
            for(int j=0;j<2;j++){ int k=k0+ty*2+j; float v=accr[i][j]-she[ty*2+j];
                if(v>bb||(v==bb&&k<bk)){ bb=v; bk=k; } }
            rv[ty*16+tx*4+i]=bb; rk[ty*16+tx*4+i]=bk;
        }
        __syncthreads();
        if(tid<16){
            float bv=rv[tid]; int bk=rk[tid];
            for(int y=1;y<64;y++){ float v=rv[y*16+tid]; int kk=rk[y*16+tid];
                if(v>bv||(v==bv&&kk<bk)){ bv=v; bk=kk; } }
            if(tid<cnt){
                float s=-bv;
                uint32_t bits=__float_as_uint(s);
                uint32_t ord = bits ^ ((bits>>31) ? 0xFFFFFFFFu : 0x80000000u);
                unsigned long long key = ((unsigned long long)ord<<32) | (uint32_t)bk;
                atomicMin(&g_best[srows[tid]], key);
            }
        }
        __syncthreads();
    }
}

// ---------- outputs: decode 2 d-groups per thread ----------
__global__ void decode_emit_kernel(float* __restrict__ dec, float* __restrict__ codes_out){
    int i = blockIdx.x*256+threadIdx.x;       // < PBT*32
    int t = i & 4095;
    int dg = (i>>12) & 31;
    int b = i >> 17;
    int code = (int)(g_best[b*PT+t]&0xFFFFFFFFull);
    const float* er = &g_emb[code*PD];
    float4 e0 = *(const float4*)&er[dg*4];
    float4 e1 = *(const float4*)&er[dg*4+128];
    if(dec){
        long base = ((long)b<<20) + ((long)dg<<14) + t;
        dec[base]          = e0.x;
        dec[base+4096]     = e0.y;
        dec[base+8192]     = e0.z;
        dec[base+12288]    = e0.w;
        long base2 = base + (1L<<19);
        dec[base2]         = e1.x;
        dec[base2+4096]    = e1.y;
        dec[base2+8192]    = e1.z;
        dec[base2+12288]   = e1.w;
    }
    if(codes_out && i<PBT) codes_out[i]=(float)(int)(g_best[i]&0xFFFFFFFFull);
}
__global__ void emit_codes_i_kernel(int* o){ int i=blockIdx.x*256+threadIdx.x; o[i]=(int)(g_best[i]&0xFFFFFFFFull); }

extern "C" void kernel_launch(void* const* d_in, const int* in_sizes, int n_in,
                              void* d_out, int out_size){
    const float* x=(const float*)d_in[0];
    const float* esum=(const float*)d_in[1];
    const float* cu=(const float*)d_in[2];

    prep_emb_kernel<<<PK,256>>>(esum,cu);

    cudaFuncSetAttribute(argmin_mma_kernel,cudaFuncAttributeMaxDynamicSharedMemorySize,SMEMB);
    cudaFuncSetAttribute(recheck_kernel,cudaFuncAttributeMaxDynamicSharedMemorySize,RSMEM);
    argmin_mma_kernel<<<PBT/128,256,SMEMB>>>(x);
    recheck_kernel<<<dim3(128,16),256,RSMEM>>>(x);

    float* codes_out=nullptr; float* dec_out=nullptr; bool ci=false;
    if(out_size==PBT+NDEC){ codes_out=(float*)d_out; dec_out=(float*)d_out+PBT; }
    else if(out_size==NDEC){ dec_out=(float*)d_out; }
    else if(out_size==PBT){ ci=true; }
    else { codes_out=(float*)d_out; if(out_size>=PBT+NDEC) dec_out=(float*)d_out+PBT; }

    if(dec_out||codes_out) decode_emit_kernel<<<(PBT*32)/256,256>>>(dec_out,codes_out);
    if(ci) emit_codes_i_kernel<<<PBT/256,256>>>((int*)d_out);
}